// round 3
// baseline (speedup 1.0000x reference)
#include <cuda_runtime.h>
#include <cuda_bf16.h>
#include <cstdint>
#include <cstddef>

// ============================================================================
// TripletSTDP: B=32, T=512, N_PRE=N_POST=1024.
// wu = (1/(B*T)) * (A @ B^T), K = 2*B*T = 32768
//   A[m][k]: k<16384 -> R trace of pre (decayed), k>=16384 -> pre spike
//   B[n][k]: k<16384 -> post spike,               k>=16384 -> -O trace of post
// A and B are stored PRE-PERMUTED in mma.m16n8k16 fragment order so the GEMM
// needs no shared memory and no ldmatrix: one LDG.128 per fragment.
// ============================================================================

static __device__ __align__(128) __nv_bfloat16 g_A[1024ull * 32768ull]; // 64 MB
static __device__ __align__(128) __nv_bfloat16 g_B[1024ull * 32768ull]; // 64 MB
static __device__ __align__(128) float         g_WS[4ull * 1024ull * 1024ull]; // split-K partials

// ---------------------------------------------------------------------------
// mma.sync bf16 (generic PTX, works on compute_103 virtual arch)
// ---------------------------------------------------------------------------
__device__ __forceinline__ void mma_bf16(float* d, const uint32_t* a,
                                         uint32_t b0, uint32_t b1) {
    asm volatile(
        "mma.sync.aligned.m16n8k16.row.col.f32.bf16.bf16.f32 "
        "{%0,%1,%2,%3}, {%4,%5,%6,%7}, {%8,%9}, {%0,%1,%2,%3};"
        : "+f"(d[0]), "+f"(d[1]), "+f"(d[2]), "+f"(d[3])
        : "r"(a[0]), "r"(a[1]), "r"(a[2]), "r"(a[3]), "r"(b0), "r"(b1));
}

// ---------------------------------------------------------------------------
// Kernel 1: trace scan + fragment-layout store.
// grid (8 p-tiles, 32 batch, 2 sides), 128 threads.
//
// Fragment layouts (16B units, per lane of a 32-lane fragment block):
//  A: addr16 = ((mt*2048 + ks)*8  + mfrag)*32 + lane      (mt: 128-row tiles)
//     .x=a0(m0,k0..k0+1) .y=a1(m0+8) .z=a2(k0+8) .w=a3(m0+8,k0+8)
//     m0 = mfrag*16 + (lane>>2), k0 = ks*16 + (lane&3)*2
//  B: addr16 = ((nt*2048 + ks)*16 + n16 )*32 + lane       (nt: 256-col tiles)
//     .x=b0(even n8) .y=b0(odd n8) .z=b1(even n8) .w=b1(odd n8)
//     n_even = n16*16 + (lane>>2), n_odd = +8, k0 = ks*16 + (lane&3)*2
//     (GEMM consumes (.x,.z) for even n8 and (.y,.w) for odd n8)
// ---------------------------------------------------------------------------
__global__ void __launch_bounds__(128) stdp_scan_kernel(const float* __restrict__ pre,
                                                        const float* __restrict__ post)
{
    const int side = blockIdx.z;                 // 0: pre -> g_A, 1: post -> g_B
    const float* __restrict__ in = side ? post : pre;
    __nv_bfloat16* mat = side ? g_B : g_A;
    const int b   = blockIdx.y;
    const int bx  = blockIdx.x;
    const int tid = threadIdx.x;
    const int p0  = bx * 128;

    const float dA = 0.95122942f;                      // exp(-1/20)
    const float dB = side ? 0.99126643f : 0.99014786f; // exp(-1/114) / exp(-1/101)
    const float c1 = side ? 0.00525f : 0.005f;         // A_MINUS / A_PLUS
    const float c2 = 0.0001f;                          // triplet coeff

    __shared__ __align__(16) __nv_bfloat16 s1[128][72];
    __shared__ __align__(16) __nv_bfloat16 s2[128][72];

    float t1 = 0.f, t2 = 0.f;
    const float* src = in + (size_t)b * (512 * 1024) + p0 + tid;

    for (int ch = 0; ch < 8; ++ch) {
        #pragma unroll
        for (int tt = 0; tt < 64; ++tt) {
            float x = src[(size_t)(ch * 64 + tt) * 1024];
            t1 *= dA; t2 *= dB;                           // decay first
            float tr = fmaf(c2 * t1, t2, c1 * t1);        // c1*r1 + c2*r1*r2
            s1[tid][tt] = __float2bfloat16(side ? x : tr);   // first K half
            s2[tid][tt] = __float2bfloat16(side ? -tr : x);  // second K half
            t1 += x; t2 += x;                             // then add spike
        }
        __syncthreads();
        const int ksbase = b * 32 + ch * 4;               // global k_step base
        uint4* mat4 = reinterpret_cast<uint4*>(mat);
        #pragma unroll
        for (int it = 0; it < 8; ++it) {
            int f    = it * 128 + tid;   // fragment-slot id: 0..1023
            int lane = f & 31;
            int ksl  = (f >> 5) & 3;
            int frag = f >> 7;           // 0..7 (mfrag / n16-within-128)
            int gid  = lane >> 2, tig = lane & 3;
            int pr   = frag * 16 + gid;
            int tb   = ksl * 16 + tig * 2;
            uint4 w1, w2;
            w1.x = *(const uint32_t*)&s1[pr    ][tb    ];
            w1.y = *(const uint32_t*)&s1[pr + 8][tb    ];
            w1.z = *(const uint32_t*)&s1[pr    ][tb + 8];
            w1.w = *(const uint32_t*)&s1[pr + 8][tb + 8];
            w2.x = *(const uint32_t*)&s2[pr    ][tb    ];
            w2.y = *(const uint32_t*)&s2[pr + 8][tb    ];
            w2.z = *(const uint32_t*)&s2[pr    ][tb + 8];
            w2.w = *(const uint32_t*)&s2[pr + 8][tb + 8];
            int ks = ksbase + ksl;
            size_t d16, half;
            if (side == 0) {   // A: m-frag layout
                d16  = ((size_t)(bx * 2048 + ks) * 8 + frag) * 32 + lane;
                half = 1024ull * 8 * 32;       // +16384 k = +1024 ksteps
            } else {           // B: n-pack layout
                d16  = ((size_t)((bx >> 1) * 2048 + ks) * 16 + (bx & 1) * 8 + frag) * 32 + lane;
                half = 1024ull * 16 * 32;
            }
            mat4[d16]        = w1;
            mat4[d16 + half] = w2;
        }
        __syncthreads();
    }
}

// ---------------------------------------------------------------------------
// Kernel 2: bf16 mma.sync GEMM, no smem. CTA tile 128x256, warps 2(M)x4(N),
// warp tile 64x64, split-K=4 -> grid(8,4,4), 256 threads, double-buffered LDG.
// ---------------------------------------------------------------------------
__global__ void __launch_bounds__(256, 1) stdp_gemm_kernel()
{
    const int tid  = threadIdx.x;
    const int lane = tid & 31;
    const int wid  = tid >> 5;
    const int wm   = wid & 1;     // 0..1  (M direction)
    const int wn   = wid >> 1;    // 0..3  (N direction)
    const int mt   = blockIdx.x;  // 0..7
    const int nt   = blockIdx.y;  // 0..3
    const int kz   = blockIdx.z;  // 0..3 split-K

    // base pointers in uint4 (16B fragment) units
    const uint4* pa = reinterpret_cast<const uint4*>(g_A)
                    + ((size_t)(mt * 2048 + kz * 512) * 8 + wm * 4) * 32 + lane;
    const uint4* pb = reinterpret_cast<const uint4*>(g_B)
                    + ((size_t)(nt * 2048 + kz * 512) * 16 + wn * 4) * 32 + lane;

    float acc[4][8][4];
    #pragma unroll
    for (int i = 0; i < 4; ++i)
        #pragma unroll
        for (int j = 0; j < 8; ++j)
            #pragma unroll
            for (int c = 0; c < 4; ++c) acc[i][j][c] = 0.f;

    uint4 ab[2][4], bb[2][4];
    #pragma unroll
    for (int i = 0; i < 4; ++i) ab[0][i] = pa[i * 32];
    #pragma unroll
    for (int j = 0; j < 4; ++j) bb[0][j] = pb[j * 32];

    #pragma unroll 2
    for (int it = 0; it < 512; ++it) {
        const int cur = it & 1;
        if (it + 1 < 512) {
            pa += 256;              // next k_step: 8 frags * 32 lanes
            pb += 512;              // next k_step: 16 packs * 32 lanes
            #pragma unroll
            for (int i = 0; i < 4; ++i) ab[cur ^ 1][i] = pa[i * 32];
            #pragma unroll
            for (int j = 0; j < 4; ++j) bb[cur ^ 1][j] = pb[j * 32];
        }
        #pragma unroll
        for (int i = 0; i < 4; ++i) {
            const uint32_t* a = reinterpret_cast<const uint32_t*>(&ab[cur][i]);
            #pragma unroll
            for (int j = 0; j < 4; ++j) {
                // even n8 uses (b0=.x, b1=.z); odd n8 uses (b0=.y, b1=.w)
                mma_bf16(acc[i][2 * j + 0], a, bb[cur][j].x, bb[cur][j].z);
                mma_bf16(acc[i][2 * j + 1], a, bb[cur][j].y, bb[cur][j].w);
            }
        }
    }

    // epilogue: write split-K partial to workspace
    const int gid = lane >> 2, tig = lane & 3;
    float* wsbase = g_WS + ((size_t)kz << 20);
    #pragma unroll
    for (int i = 0; i < 4; ++i) {
        int row0 = mt * 128 + (wm * 4 + i) * 16 + gid;
        #pragma unroll
        for (int j = 0; j < 8; ++j) {
            int col = nt * 256 + (wn * 4 + (j >> 1)) * 16 + (j & 1) * 8 + tig * 2;
            float* d0 = wsbase + (size_t)row0 * 1024 + col;
            d0[0] = acc[i][j][0];
            d0[1] = acc[i][j][1];
            float* d1 = d0 + 8 * 1024;
            d1[0] = acc[i][j][2];
            d1[1] = acc[i][j][3];
        }
    }
}

// ---------------------------------------------------------------------------
// Kernel 3: reduce split-K partials + scale 1/(B*T). Deterministic.
// ---------------------------------------------------------------------------
__global__ void __launch_bounds__(256) stdp_reduce_kernel(float* __restrict__ out)
{
    int i = blockIdx.x * 256 + threadIdx.x;    // float4 units, 0..262143
    const float4* w = reinterpret_cast<const float4*>(g_WS);
    float4 a = w[i];
    float4 b = w[i + 262144];
    float4 c = w[i + 524288];
    float4 d = w[i + 786432];
    const float s = 1.0f / 16384.0f;
    float4 r;
    r.x = (a.x + b.x + c.x + d.x) * s;
    r.y = (a.y + b.y + c.y + d.y) * s;
    r.z = (a.z + b.z + c.z + d.z) * s;
    r.w = (a.w + b.w + c.w + d.w) * s;
    reinterpret_cast<float4*>(out)[i] = r;
}

// ---------------------------------------------------------------------------
extern "C" void kernel_launch(void* const* d_in, const int* in_sizes, int n_in,
                              void* d_out, int out_size)
{
    (void)in_sizes; (void)n_in; (void)out_size;
    const float* pre  = (const float*)d_in[0];
    const float* post = (const float*)d_in[1];
    float* out = (float*)d_out;

    stdp_scan_kernel<<<dim3(8, 32, 2), 128>>>(pre, post);
    stdp_gemm_kernel<<<dim3(8, 4, 4), 256>>>();
    stdp_reduce_kernel<<<1024, 256>>>(out);
}

// round 4
// speedup vs baseline: 1.6053x; 1.6053x over previous
#include <cuda_runtime.h>
#include <cuda_bf16.h>
#include <cstdint>
#include <cstddef>

// ============================================================================
// TripletSTDP: B=32, T=512, N_PRE=N_POST=1024.
// wu = (1/(B*T)) * (A @ B^T), K = 2*B*T = 32768
//   A[m][k]: k<16384 -> R trace of pre (decayed), k>=16384 -> pre spike
//   B[n][k]: k<16384 -> post spike,               k>=16384 -> -O trace of post
// A and B are stored PRE-PERMUTED in mma.m16n8k16 fragment order. The GEMM
// stages contiguous k64 chunks through smem with a 4-deep cp.async pipeline.
// ============================================================================

static __device__ __align__(128) __nv_bfloat16 g_A[1024ull * 32768ull]; // 64 MB
static __device__ __align__(128) __nv_bfloat16 g_B[1024ull * 32768ull]; // 64 MB
static __device__ __align__(128) float         g_WS[4ull * 1024ull * 1024ull]; // split-K partials

// ---------------------------------------------------------------------------
__device__ __forceinline__ void mma_bf16(float* d, const uint32_t* a,
                                         uint32_t b0, uint32_t b1) {
    asm volatile(
        "mma.sync.aligned.m16n8k16.row.col.f32.bf16.bf16.f32 "
        "{%0,%1,%2,%3}, {%4,%5,%6,%7}, {%8,%9}, {%0,%1,%2,%3};"
        : "+f"(d[0]), "+f"(d[1]), "+f"(d[2]), "+f"(d[3])
        : "r"(a[0]), "r"(a[1]), "r"(a[2]), "r"(a[3]), "r"(b0), "r"(b1));
}
__device__ __forceinline__ uint32_t smem_u32(const void* p) {
    uint32_t a;
    asm("{ .reg .u64 t; cvta.to.shared.u64 t, %1; cvt.u32.u64 %0, t; }" : "=r"(a) : "l"(p));
    return a;
}
__device__ __forceinline__ void cp16(uint32_t dst, const void* src) {
    asm volatile("cp.async.cg.shared.global [%0], [%1], 16;" :: "r"(dst), "l"(src));
}

// ---------------------------------------------------------------------------
// Kernel 1: trace scan + fragment-layout store (unchanged from R3, passing).
// grid (8 p-tiles, 32 batch, 2 sides), 128 threads.
//  A: addr16 = ((mt*2048 + ks)*8  + mfrag)*32 + lane
//     .x=a0(m0,k0..k0+1) .y=a1(m0+8) .z=a2(k0+8) .w=a3(m0+8,k0+8)
//  B: addr16 = ((nt*2048 + ks)*16 + n16 )*32 + lane
//     .x=b0(even n8) .y=b0(odd n8) .z=b1(even n8) .w=b1(odd n8)
// ---------------------------------------------------------------------------
__global__ void __launch_bounds__(128) stdp_scan_kernel(const float* __restrict__ pre,
                                                        const float* __restrict__ post)
{
    const int side = blockIdx.z;
    const float* __restrict__ in = side ? post : pre;
    __nv_bfloat16* mat = side ? g_B : g_A;
    const int b   = blockIdx.y;
    const int bx  = blockIdx.x;
    const int tid = threadIdx.x;
    const int p0  = bx * 128;

    const float dA = 0.95122942f;                      // exp(-1/20)
    const float dB = side ? 0.99126643f : 0.99014786f; // exp(-1/114) / exp(-1/101)
    const float c1 = side ? 0.00525f : 0.005f;         // A_MINUS / A_PLUS
    const float c2 = 0.0001f;

    __shared__ __align__(16) __nv_bfloat16 s1[128][72];
    __shared__ __align__(16) __nv_bfloat16 s2[128][72];

    float t1 = 0.f, t2 = 0.f;
    const float* src = in + (size_t)b * (512 * 1024) + p0 + tid;

    for (int ch = 0; ch < 8; ++ch) {
        #pragma unroll
        for (int tt = 0; tt < 64; ++tt) {
            float x = src[(size_t)(ch * 64 + tt) * 1024];
            t1 *= dA; t2 *= dB;
            float tr = fmaf(c2 * t1, t2, c1 * t1);
            s1[tid][tt] = __float2bfloat16(side ? x : tr);
            s2[tid][tt] = __float2bfloat16(side ? -tr : x);
            t1 += x; t2 += x;
        }
        __syncthreads();
        const int ksbase = b * 32 + ch * 4;
        uint4* mat4 = reinterpret_cast<uint4*>(mat);
        #pragma unroll
        for (int it = 0; it < 8; ++it) {
            int f    = it * 128 + tid;
            int lane = f & 31;
            int ksl  = (f >> 5) & 3;
            int frag = f >> 7;
            int gid  = lane >> 2, tig = lane & 3;
            int pr   = frag * 16 + gid;
            int tb   = ksl * 16 + tig * 2;
            uint4 w1, w2;
            w1.x = *(const uint32_t*)&s1[pr    ][tb    ];
            w1.y = *(const uint32_t*)&s1[pr + 8][tb    ];
            w1.z = *(const uint32_t*)&s1[pr    ][tb + 8];
            w1.w = *(const uint32_t*)&s1[pr + 8][tb + 8];
            w2.x = *(const uint32_t*)&s2[pr    ][tb    ];
            w2.y = *(const uint32_t*)&s2[pr + 8][tb    ];
            w2.z = *(const uint32_t*)&s2[pr    ][tb + 8];
            w2.w = *(const uint32_t*)&s2[pr + 8][tb + 8];
            int ks = ksbase + ksl;
            size_t d16, half;
            if (side == 0) {
                d16  = ((size_t)(bx * 2048 + ks) * 8 + frag) * 32 + lane;
                half = 1024ull * 8 * 32;
            } else {
                d16  = ((size_t)((bx >> 1) * 2048 + ks) * 16 + (bx & 1) * 8 + frag) * 32 + lane;
                half = 1024ull * 16 * 32;
            }
            mat4[d16]        = w1;
            mat4[d16 + half] = w2;
        }
        __syncthreads();
    }
}

// ---------------------------------------------------------------------------
// Kernel 2: bf16 mma.sync GEMM, smem-staged. CTA tile 128x256, 8 warps (2x4),
// warp tile 64x64, split-K=4 -> grid(8,4,4) = 128 CTAs (one wave).
// 4-stage cp.async pipeline of contiguous k64 chunks (A 16KB + B 32KB).
// ---------------------------------------------------------------------------
constexpr int      GEMM_STAGES   = 4;
constexpr int      CHUNK_U4      = 3072;                  // 1024 A + 2048 B uint4s
constexpr uint32_t GEMM_SMEM_B   = GEMM_STAGES * CHUNK_U4 * 16; // 196608 B

__global__ void __launch_bounds__(256, 1) stdp_gemm_kernel()
{
    extern __shared__ __align__(16) uint4 sm[];           // [4][3072]
    const int tid  = threadIdx.x;
    const int lane = tid & 31;
    const int wid  = tid >> 5;
    const int wm   = wid & 1;     // M direction (0..1)
    const int wn   = wid >> 1;    // N direction (0..3)
    const int mt   = blockIdx.x;  // 0..7
    const int nt   = blockIdx.y;  // 0..3
    const int kz   = blockIdx.z;  // 0..3 split-K

    // contiguous chunk sources (fragment-ordered gmem)
    const uint4* gA = reinterpret_cast<const uint4*>(g_A)
                    + (size_t)(mt * 2048 + kz * 512) * 8 * 32;   // + c*1024
    const uint4* gB = reinterpret_cast<const uint4*>(g_B)
                    + (size_t)(nt * 2048 + kz * 512) * 16 * 32;  // + c*2048

    const uint32_t smb = smem_u32(sm);

    // fill chunk c into stage s (pure linear block copy)
    auto fill = [&](int c, int s) {
        uint32_t stA = smb + (uint32_t)s * (CHUNK_U4 * 16);
        uint32_t stB = stA + 1024 * 16;
        const uint4* srcA = gA + (size_t)c * 1024;
        const uint4* srcB = gB + (size_t)c * 2048;
        #pragma unroll
        for (int i = 0; i < 4; ++i)
            cp16(stA + (uint32_t)(tid + i * 256) * 16, srcA + tid + i * 256);
        #pragma unroll
        for (int i = 0; i < 8; ++i)
            cp16(stB + (uint32_t)(tid + i * 256) * 16, srcB + tid + i * 256);
    };

    float acc[4][8][4];
    #pragma unroll
    for (int i = 0; i < 4; ++i)
        #pragma unroll
        for (int j = 0; j < 8; ++j)
            #pragma unroll
            for (int c = 0; c < 4; ++c) acc[i][j][c] = 0.f;

    // prologue: stages 0..2
    #pragma unroll
    for (int f = 0; f < GEMM_STAGES - 1; ++f) {
        fill(f, f);
        asm volatile("cp.async.commit_group;" ::: "memory");
    }

    for (int c = 0; c < 128; ++c) {
        asm volatile("cp.async.wait_group %0;" :: "n"(GEMM_STAGES - 2) : "memory");
        __syncthreads();   // chunk c resident; all warps done reading stage (c-1)%4

        int nf = c + GEMM_STAGES - 1;
        if (nf < 128) fill(nf, nf & 3);
        asm volatile("cp.async.commit_group;" ::: "memory");  // commit (possibly empty)

        const uint4* sA = sm + (c & 3) * CHUNK_U4;
        const uint4* sB = sA + 1024;
        #pragma unroll
        for (int ksl = 0; ksl < 4; ++ksl) {
            uint4 af[4], bf[4];
            #pragma unroll
            for (int i = 0; i < 4; ++i)
                af[i] = sA[(ksl * 8 + wm * 4 + i) * 32 + lane];
            #pragma unroll
            for (int j = 0; j < 4; ++j)
                bf[j] = sB[(ksl * 16 + wn * 4 + j) * 32 + lane];
            #pragma unroll
            for (int i = 0; i < 4; ++i) {
                const uint32_t* a = reinterpret_cast<const uint32_t*>(&af[i]);
                #pragma unroll
                for (int j = 0; j < 4; ++j) {
                    mma_bf16(acc[i][2 * j + 0], a, bf[j].x, bf[j].z); // even n8
                    mma_bf16(acc[i][2 * j + 1], a, bf[j].y, bf[j].w); // odd n8
                }
            }
        }
    }

    // epilogue: write split-K partial to workspace
    const int gid = lane >> 2, tig = lane & 3;
    float* wsbase = g_WS + ((size_t)kz << 20);
    #pragma unroll
    for (int i = 0; i < 4; ++i) {
        int row0 = mt * 128 + (wm * 4 + i) * 16 + gid;
        #pragma unroll
        for (int j = 0; j < 8; ++j) {
            int col = nt * 256 + (wn * 4 + (j >> 1)) * 16 + (j & 1) * 8 + tig * 2;
            float* d0 = wsbase + (size_t)row0 * 1024 + col;
            d0[0] = acc[i][j][0];
            d0[1] = acc[i][j][1];
            float* d1 = d0 + 8 * 1024;
            d1[0] = acc[i][j][2];
            d1[1] = acc[i][j][3];
        }
    }
}

// ---------------------------------------------------------------------------
// Kernel 3: reduce split-K partials + scale 1/(B*T). Deterministic.
// ---------------------------------------------------------------------------
__global__ void __launch_bounds__(256) stdp_reduce_kernel(float* __restrict__ out)
{
    int i = blockIdx.x * 256 + threadIdx.x;
    const float4* w = reinterpret_cast<const float4*>(g_WS);
    float4 a = w[i];
    float4 b = w[i + 262144];
    float4 c = w[i + 524288];
    float4 d = w[i + 786432];
    const float s = 1.0f / 16384.0f;
    float4 r;
    r.x = (a.x + b.x + c.x + d.x) * s;
    r.y = (a.y + b.y + c.y + d.y) * s;
    r.z = (a.z + b.z + c.z + d.z) * s;
    r.w = (a.w + b.w + c.w + d.w) * s;
    reinterpret_cast<float4*>(out)[i] = r;
}

// ---------------------------------------------------------------------------
extern "C" void kernel_launch(void* const* d_in, const int* in_sizes, int n_in,
                              void* d_out, int out_size)
{
    (void)in_sizes; (void)n_in; (void)out_size;
    const float* pre  = (const float*)d_in[0];
    const float* post = (const float*)d_in[1];
    float* out = (float*)d_out;

    stdp_scan_kernel<<<dim3(8, 32, 2), 128>>>(pre, post);

    cudaFuncSetAttribute(stdp_gemm_kernel,
                         cudaFuncAttributeMaxDynamicSharedMemorySize, GEMM_SMEM_B);
    stdp_gemm_kernel<<<dim3(8, 4, 4), 256, GEMM_SMEM_B>>>();

    stdp_reduce_kernel<<<1024, 256>>>(out);
}

// round 5
// speedup vs baseline: 1.9117x; 1.1909x over previous
#include <cuda_runtime.h>
#include <cuda_bf16.h>
#include <cstdint>
#include <cstddef>

// ============================================================================
// TripletSTDP: B=32, T=512, N_PRE=N_POST=1024.
// wu = (1/(B*T)) * (A @ B^T), K = 2*B*T = 32768
//   A[m][k]: k<16384 -> R trace of pre (decayed), k>=16384 -> pre spike
//   B[n][k]: k<16384 -> post spike,               k>=16384 -> -O trace of post
// A and B stored PRE-PERMUTED in mma.m16n8k16 fragment order; GEMM stages
// contiguous k64 chunks via 4-deep cp.async pipeline with register-level
// fragment prefetch across the chunk barrier.
// ============================================================================

static __device__ __align__(128) __nv_bfloat16 g_A[1024ull * 32768ull]; // 64 MB
static __device__ __align__(128) __nv_bfloat16 g_B[1024ull * 32768ull]; // 64 MB
static __device__ __align__(128) float         g_WS[4ull * 1024ull * 1024ull]; // split-K partials

// ---------------------------------------------------------------------------
__device__ __forceinline__ void mma_bf16(float* d, const uint32_t* a,
                                         uint32_t b0, uint32_t b1) {
    asm volatile(
        "mma.sync.aligned.m16n8k16.row.col.f32.bf16.bf16.f32 "
        "{%0,%1,%2,%3}, {%4,%5,%6,%7}, {%8,%9}, {%0,%1,%2,%3};"
        : "+f"(d[0]), "+f"(d[1]), "+f"(d[2]), "+f"(d[3])
        : "r"(a[0]), "r"(a[1]), "r"(a[2]), "r"(a[3]), "r"(b0), "r"(b1));
}
__device__ __forceinline__ uint32_t smem_u32(const void* p) {
    uint32_t a;
    asm("{ .reg .u64 t; cvta.to.shared.u64 t, %1; cvt.u32.u64 %0, t; }" : "=r"(a) : "l"(p));
    return a;
}
__device__ __forceinline__ void cp16(uint32_t dst, const void* src) {
    asm volatile("cp.async.cg.shared.global [%0], [%1], 16;" :: "r"(dst), "l"(src));
}

// ---------------------------------------------------------------------------
// Kernel 1: trace scan + fragment-layout store (unchanged; passing).
// ---------------------------------------------------------------------------
__global__ void __launch_bounds__(128) stdp_scan_kernel(const float* __restrict__ pre,
                                                        const float* __restrict__ post)
{
    const int side = blockIdx.z;
    const float* __restrict__ in = side ? post : pre;
    __nv_bfloat16* mat = side ? g_B : g_A;
    const int b   = blockIdx.y;
    const int bx  = blockIdx.x;
    const int tid = threadIdx.x;
    const int p0  = bx * 128;

    const float dA = 0.95122942f;                      // exp(-1/20)
    const float dB = side ? 0.99126643f : 0.99014786f; // exp(-1/114) / exp(-1/101)
    const float c1 = side ? 0.00525f : 0.005f;         // A_MINUS / A_PLUS
    const float c2 = 0.0001f;

    __shared__ __align__(16) __nv_bfloat16 s1[128][72];
    __shared__ __align__(16) __nv_bfloat16 s2[128][72];

    float t1 = 0.f, t2 = 0.f;
    const float* src = in + (size_t)b * (512 * 1024) + p0 + tid;

    for (int ch = 0; ch < 8; ++ch) {
        #pragma unroll
        for (int tt = 0; tt < 64; ++tt) {
            float x = src[(size_t)(ch * 64 + tt) * 1024];
            t1 *= dA; t2 *= dB;
            float tr = fmaf(c2 * t1, t2, c1 * t1);
            s1[tid][tt] = __float2bfloat16(side ? x : tr);
            s2[tid][tt] = __float2bfloat16(side ? -tr : x);
            t1 += x; t2 += x;
        }
        __syncthreads();
        const int ksbase = b * 32 + ch * 4;
        uint4* mat4 = reinterpret_cast<uint4*>(mat);
        #pragma unroll
        for (int it = 0; it < 8; ++it) {
            int f    = it * 128 + tid;
            int lane = f & 31;
            int ksl  = (f >> 5) & 3;
            int frag = f >> 7;
            int gid  = lane >> 2, tig = lane & 3;
            int pr   = frag * 16 + gid;
            int tb   = ksl * 16 + tig * 2;
            uint4 w1, w2;
            w1.x = *(const uint32_t*)&s1[pr    ][tb    ];
            w1.y = *(const uint32_t*)&s1[pr + 8][tb    ];
            w1.z = *(const uint32_t*)&s1[pr    ][tb + 8];
            w1.w = *(const uint32_t*)&s1[pr + 8][tb + 8];
            w2.x = *(const uint32_t*)&s2[pr    ][tb    ];
            w2.y = *(const uint32_t*)&s2[pr + 8][tb    ];
            w2.z = *(const uint32_t*)&s2[pr    ][tb + 8];
            w2.w = *(const uint32_t*)&s2[pr + 8][tb + 8];
            int ks = ksbase + ksl;
            size_t d16, half;
            if (side == 0) {
                d16  = ((size_t)(bx * 2048 + ks) * 8 + frag) * 32 + lane;
                half = 1024ull * 8 * 32;
            } else {
                d16  = ((size_t)((bx >> 1) * 2048 + ks) * 16 + (bx & 1) * 8 + frag) * 32 + lane;
                half = 1024ull * 16 * 32;
            }
            mat4[d16]        = w1;
            mat4[d16 + half] = w2;
        }
        __syncthreads();
    }
}

// ---------------------------------------------------------------------------
// Kernel 2: bf16 mma.sync GEMM, smem-staged. CTA 128x256, 8 warps (2Mx4N),
// warp tile 64x64, split-K=4 -> grid(8,4,4) = 128 CTAs.
// 4-stage cp.async pipeline; wait_group(1) keeps chunks c AND c+1 resident
// so fragments are register-prefetched across the chunk barrier.
// ---------------------------------------------------------------------------
constexpr int      GEMM_STAGES = 4;
constexpr int      CHUNK_U4    = 3072;                       // 1024 A + 2048 B uint4
constexpr uint32_t GEMM_SMEM_B = GEMM_STAGES * CHUNK_U4 * 16; // 196608 B

__global__ void __launch_bounds__(256, 1) stdp_gemm_kernel()
{
    extern __shared__ __align__(16) uint4 sm[];              // [4][3072]
    const int tid  = threadIdx.x;
    const int lane = tid & 31;
    const int wid  = tid >> 5;
    const int wm   = wid & 1;
    const int wn   = wid >> 1;
    const int mt   = blockIdx.x;
    const int nt   = blockIdx.y;
    const int kz   = blockIdx.z;

    const uint4* gA = reinterpret_cast<const uint4*>(g_A)
                    + (size_t)(mt * 2048 + kz * 512) * 8 * 32;
    const uint4* gB = reinterpret_cast<const uint4*>(g_B)
                    + (size_t)(nt * 2048 + kz * 512) * 16 * 32;

    const uint32_t smb = smem_u32(sm);

    auto fill = [&](int c, int s) {
        uint32_t stA = smb + (uint32_t)s * (CHUNK_U4 * 16);
        uint32_t stB = stA + 1024 * 16;
        const uint4* srcA = gA + (size_t)c * 1024;
        const uint4* srcB = gB + (size_t)c * 2048;
        #pragma unroll
        for (int i = 0; i < 4; ++i)
            cp16(stA + (uint32_t)(tid + i * 256) * 16, srcA + tid + i * 256);
        #pragma unroll
        for (int i = 0; i < 8; ++i)
            cp16(stB + (uint32_t)(tid + i * 256) * 16, srcB + tid + i * 256);
    };
    // fragment smem addresses for (chunk, ksl)
    auto aAddr = [&](int c, int ksl, int i) -> const uint4* {
        return sm + (c & 3) * CHUNK_U4 + (size_t)(ksl * 8 + wm * 4 + i) * 32 + lane;
    };
    auto bAddr = [&](int c, int ksl, int j) -> const uint4* {
        return sm + (c & 3) * CHUNK_U4 + 1024 + (size_t)(ksl * 16 + wn * 4 + j) * 32 + lane;
    };

    float acc[4][8][4];
    #pragma unroll
    for (int i = 0; i < 4; ++i)
        #pragma unroll
        for (int j = 0; j < 8; ++j)
            #pragma unroll
            for (int c = 0; c < 4; ++c) acc[i][j][c] = 0.f;

    // prologue: fill chunks 0,1,2; ensure 0 and 1 resident.
    #pragma unroll
    for (int f = 0; f < 3; ++f) {
        fill(f, f);
        asm volatile("cp.async.commit_group;" ::: "memory");
    }
    asm volatile("cp.async.wait_group 1;" ::: "memory");
    __syncthreads();

    uint4 af[2][4], bf[2][4];
    #pragma unroll
    for (int i = 0; i < 4; ++i) af[0][i] = *aAddr(0, 0, i);
    #pragma unroll
    for (int j = 0; j < 4; ++j) bf[0][j] = *bAddr(0, 0, j);

    for (int c = 0; c < 128; ++c) {
        // compute 4 k-slices of chunk c; prefetch next slice (or next chunk's
        // slice 0 — chunk c+1 is guaranteed resident) into the other buffer.
        #pragma unroll
        for (int ksl = 0; ksl < 4; ++ksl) {
            const int cur = ksl & 1;
            const int nxt = cur ^ 1;
            const int pc  = (ksl == 3) ? (c + 1) : c;   // c+1 reads wrap mod 4; c=127 prefetch is dead but stage 0 is valid memory
            const int pk  = (ksl + 1) & 3;
            #pragma unroll
            for (int i = 0; i < 4; ++i) af[nxt][i] = *aAddr(pc & 127 ? pc : pc, pk, i);
            #pragma unroll
            for (int j = 0; j < 4; ++j) bf[nxt][j] = *bAddr(pc, pk, j);
            #pragma unroll
            for (int i = 0; i < 4; ++i) {
                const uint32_t* a = reinterpret_cast<const uint32_t*>(&af[cur][i]);
                #pragma unroll
                for (int j = 0; j < 4; ++j) {
                    mma_bf16(acc[i][2 * j + 0], a, bf[cur][j].x, bf[cur][j].z);
                    mma_bf16(acc[i][2 * j + 1], a, bf[cur][j].y, bf[cur][j].w);
                }
            }
        }
        // stage maintenance for chunk c+3
        if (c + 3 < 128) fill(c + 3, (c + 3) & 3);
        asm volatile("cp.async.commit_group;" ::: "memory");
        asm volatile("cp.async.wait_group 1;" ::: "memory"); // chunk c+2 resident
        __syncthreads();  // all warps done reading chunk c; stage (c+4)&3 safe to overwrite next iter
    }

    // epilogue: write split-K partial to workspace
    const int gid = lane >> 2, tig = lane & 3;
    float* wsbase = g_WS + ((size_t)kz << 20);
    #pragma unroll
    for (int i = 0; i < 4; ++i) {
        int row0 = mt * 128 + (wm * 4 + i) * 16 + gid;
        #pragma unroll
        for (int j = 0; j < 8; ++j) {
            int col = nt * 256 + (wn * 4 + (j >> 1)) * 16 + (j & 1) * 8 + tig * 2;
            float* d0 = wsbase + (size_t)row0 * 1024 + col;
            d0[0] = acc[i][j][0];
            d0[1] = acc[i][j][1];
            float* d1 = d0 + 8 * 1024;
            d1[0] = acc[i][j][2];
            d1[1] = acc[i][j][3];
        }
    }
}

// ---------------------------------------------------------------------------
// Kernel 3: reduce split-K partials + scale 1/(B*T). Deterministic.
// ---------------------------------------------------------------------------
__global__ void __launch_bounds__(256) stdp_reduce_kernel(float* __restrict__ out)
{
    int i = blockIdx.x * 256 + threadIdx.x;
    const float4* w = reinterpret_cast<const float4*>(g_WS);
    float4 a = w[i];
    float4 b = w[i + 262144];
    float4 c = w[i + 524288];
    float4 d = w[i + 786432];
    const float s = 1.0f / 16384.0f;
    float4 r;
    r.x = (a.x + b.x + c.x + d.x) * s;
    r.y = (a.y + b.y + c.y + d.y) * s;
    r.z = (a.z + b.z + c.z + d.z) * s;
    r.w = (a.w + b.w + c.w + d.w) * s;
    reinterpret_cast<float4*>(out)[i] = r;
}

// ---------------------------------------------------------------------------
extern "C" void kernel_launch(void* const* d_in, const int* in_sizes, int n_in,
                              void* d_out, int out_size)
{
    (void)in_sizes; (void)n_in; (void)out_size;
    const float* pre  = (const float*)d_in[0];
    const float* post = (const float*)d_in[1];
    float* out = (float*)d_out;

    stdp_scan_kernel<<<dim3(8, 32, 2), 128>>>(pre, post);

    cudaFuncSetAttribute(stdp_gemm_kernel,
                         cudaFuncAttributeMaxDynamicSharedMemorySize, GEMM_SMEM_B);
    stdp_gemm_kernel<<<dim3(8, 4, 4), 256, GEMM_SMEM_B>>>();

    stdp_reduce_kernel<<<1024, 256>>>(out);
}